// round 4
// baseline (speedup 1.0000x reference)
#include <cuda_runtime.h>
#include <cuda_bf16.h>

#define NN 50000
#define EE 800000
#define RR 8
#define HH 128

typedef unsigned long long ull;

// ---------------- scratch (device globals; no allocation allowed) ----------------
__device__ float    g_xw[(size_t)RR * NN * HH];   // per-relation transformed features
__device__ float    g_sq[RR * NN];
__device__ float    g_sk[RR * NN];
__device__ float    g_alpha[EE];
__device__ unsigned g_menc[NN];
__device__ float    g_h1[(size_t)NN * HH];
__device__ float    g_h2[(size_t)NN * HH];
__device__ int      g_counts[NN];
__device__ int      g_off[NN + 1];
__device__ int      g_cursor[NN];
__device__ int      g_sorted[EE];
__device__ float    g_wlt[HH * HH];

// ---------------- helpers ----------------
__device__ __forceinline__ unsigned fenc(float f) {
    unsigned u = __float_as_uint(f);
    return (u & 0x80000000u) ? ~u : (u | 0x80000000u);
}
__device__ __forceinline__ float fdec(unsigned u) {
    unsigned b = (u & 0x80000000u) ? (u ^ 0x80000000u) : ~u;
    return __uint_as_float(b);
}

#define FMA2(d, a, b, c) \
    asm("fma.rn.f32x2 %0, %1, %2, %3;" : "=l"(d) : "l"(a), "l"(b), "l"(c))

__device__ __forceinline__ void unpack2(ull v, float& lo, float& hi) {
    asm("mov.b64 {%0, %1}, %2;" : "=f"(lo), "=f"(hi) : "l"(v));
}

// ---------------- GEMM: C[r][m][h] = sum_k A[m][k] * B[r][k][h] (+bias) ----------------
// Packed-f32x2 (FFMA2) GEMM. Block tile 128x128, K-chunk 32, 256 threads.
// Thread tile 8 rows x 8 cols (4 f32x2 pairs per row).
// Epilogue optionally computes sq[r][m] = C_row.qv, sk[r][m] = C_row.kv.
__global__ void __launch_bounds__(256)
gemm128(const float* __restrict__ A, const float* __restrict__ Bmat,
        float* __restrict__ C, int M,
        const float* __restrict__ qv, const float* __restrict__ kv,
        float* __restrict__ sq, float* __restrict__ sk,
        const float* __restrict__ bias)
{
    const int r = blockIdx.y;
    const float* B = Bmat + (size_t)r * HH * HH;
    float* Cr = C + (size_t)r * M * HH;
    const int row0 = blockIdx.x * 128;
    const int tid = threadIdx.x;
    const int tx = tid & 15;   // 16 col groups of 8
    const int ty = tid >> 4;   // 16 row groups of 8

    // A duplicated as {a,a} pairs: [128 rows][34 pair-slots] (32 used, pad to even for 16B align)
    __shared__ float2 As2[128][34];
    __shared__ float  Bs[32][132];

    ull acc[8][4];
    const ull ZER = 0ull;
#pragma unroll
    for (int i = 0; i < 8; i++)
#pragma unroll
        for (int j = 0; j < 4; j++) acc[i][j] = ZER;

    for (int k0 = 0; k0 < 128; k0 += 32) {
        // ---- load A tile 128x32, store duplicated ----
        {
            int row = tid >> 1;
            int kb = (tid & 1) * 16;
            int gr = row0 + row;
            float4 v0 = make_float4(0.f,0.f,0.f,0.f), v1 = v0, v2 = v0, v3 = v0;
            if (gr < M) {
                const float4* ap = reinterpret_cast<const float4*>(A + (size_t)gr * 128 + k0 + kb);
                v0 = ap[0]; v1 = ap[1]; v2 = ap[2]; v3 = ap[3];
            }
            float4* dst = reinterpret_cast<float4*>(&As2[row][kb]);
            dst[0] = make_float4(v0.x, v0.x, v0.y, v0.y);
            dst[1] = make_float4(v0.z, v0.z, v0.w, v0.w);
            dst[2] = make_float4(v1.x, v1.x, v1.y, v1.y);
            dst[3] = make_float4(v1.z, v1.z, v1.w, v1.w);
            dst[4] = make_float4(v2.x, v2.x, v2.y, v2.y);
            dst[5] = make_float4(v2.z, v2.z, v2.w, v2.w);
            dst[6] = make_float4(v3.x, v3.x, v3.y, v3.y);
            dst[7] = make_float4(v3.z, v3.z, v3.w, v3.w);
        }
        // ---- load B tile 32x128 ----
#pragma unroll
        for (int it = 0; it < 4; it++) {
            int idx = tid + it * 256;
            int row = idx >> 5;
            int c4 = (idx & 31) << 2;
            float4 v = *reinterpret_cast<const float4*>(B + (size_t)(k0 + row) * 128 + c4);
            *reinterpret_cast<float4*>(&Bs[row][c4]) = v;
        }
        __syncthreads();

#pragma unroll 8
        for (int k = 0; k < 32; k++) {
            ulonglong2 b01 = *reinterpret_cast<const ulonglong2*>(&Bs[k][tx << 3]);
            ulonglong2 b23 = *reinterpret_cast<const ulonglong2*>(&Bs[k][(tx << 3) + 4]);
#pragma unroll
            for (int i = 0; i < 8; i++) {
                ull a = *reinterpret_cast<const ull*>(&As2[(ty << 3) + i][k]);
                FMA2(acc[i][0], a, b01.x, acc[i][0]);
                FMA2(acc[i][1], a, b01.y, acc[i][1]);
                FMA2(acc[i][2], a, b23.x, acc[i][2]);
                FMA2(acc[i][3], a, b23.y, acc[i][3]);
            }
        }
        __syncthreads();
    }

    // ---- epilogue ----
    float q8[8], k8[8], bb8[8];
    if (qv) {
#pragma unroll
        for (int j = 0; j < 8; j++) { q8[j] = qv[(tx << 3) + j]; k8[j] = kv[(tx << 3) + j]; }
    }
    if (bias) {
#pragma unroll
        for (int j = 0; j < 8; j++) bb8[j] = bias[(tx << 3) + j];
    }

#pragma unroll
    for (int i = 0; i < 8; i++) {
        int gr = row0 + (ty << 3) + i;
        float c[8];
#pragma unroll
        for (int j = 0; j < 4; j++) unpack2(acc[i][j], c[2 * j], c[2 * j + 1]);
        if (bias) {
#pragma unroll
            for (int j = 0; j < 8; j++) c[j] += bb8[j];
        }
        if (gr < M) {
            float4* cp = reinterpret_cast<float4*>(Cr + (size_t)gr * 128 + (tx << 3));
            cp[0] = make_float4(c[0], c[1], c[2], c[3]);
            cp[1] = make_float4(c[4], c[5], c[6], c[7]);
        }
        if (qv) {
            float pq = 0.f, pk = 0.f;
#pragma unroll
            for (int j = 0; j < 8; j++) { pq += c[j] * q8[j]; pk += c[j] * k8[j]; }
#pragma unroll
            for (int off = 8; off > 0; off >>= 1) {
                pq += __shfl_down_sync(0xffffffffu, pq, off, 16);
                pk += __shfl_down_sync(0xffffffffu, pk, off, 16);
            }
            if (tx == 0 && gr < M) {
                sq[(size_t)r * M + gr] = pq;
                sk[(size_t)r * M + gr] = pk;
            }
        }
    }
}

// ---------------- CSR build (tgt is identical across both layers) ----------------
__global__ void zero_counts_kernel() {
    int n = blockIdx.x * blockDim.x + threadIdx.x;
    if (n < NN) g_counts[n] = 0;
}
__global__ void hist_kernel(const int* __restrict__ tgt) {
    int e = blockIdx.x * blockDim.x + threadIdx.x;
    if (e < EE) atomicAdd(&g_counts[tgt[e]], 1);
}
__global__ void scan_kernel() {
    __shared__ int part[1024];
    const int tid = threadIdx.x;
    const int CH = (NN + 1023) / 1024;
    const int st = tid * CH;
    int s = 0;
    for (int i = 0; i < CH; i++) {
        int idx = st + i;
        if (idx < NN) s += g_counts[idx];
    }
    part[tid] = s;
    __syncthreads();
    for (int off = 1; off < 1024; off <<= 1) {
        int add = (tid >= off) ? part[tid - off] : 0;
        __syncthreads();
        part[tid] += add;
        __syncthreads();
    }
    int run = (tid == 0) ? 0 : part[tid - 1];
    for (int i = 0; i < CH; i++) {
        int idx = st + i;
        if (idx < NN) {
            g_off[idx] = run;
            run += g_counts[idx];
        }
    }
    if (tid == 1023) g_off[NN] = part[1023];
}
__global__ void copy_cursor_kernel() {
    int n = blockIdx.x * blockDim.x + threadIdx.x;
    if (n < NN) g_cursor[n] = g_off[n];
}
__global__ void scatter_kernel(const int* __restrict__ tgt) {
    int e = blockIdx.x * blockDim.x + threadIdx.x;
    if (e < EE) {
        int pos = atomicAdd(&g_cursor[tgt[e]], 1);
        g_sorted[pos] = e;
    }
}

// ---------------- attention logits + segment max ----------------
__global__ void minit_kernel() {
    int n = blockIdx.x * blockDim.x + threadIdx.x;
    if (n < NN) g_menc[n] = 0u;
}
__global__ void alpha_kernel(const int* __restrict__ src, const int* __restrict__ tgt,
                             const int* __restrict__ et)
{
    int e = blockIdx.x * blockDim.x + threadIdx.x;
    if (e >= EE) return;
    int t = tgt[e], s = src[e], r = et[e];
    float a = g_sq[r * NN + t] + g_sk[r * NN + s];
    a = (a > 0.f) ? a : 0.2f * a;
    g_alpha[e] = a;
    atomicMax(&g_menc[t], fenc(a));
}

// ---------------- per-node softmax + weighted aggregation (no feature atomics) -------
__global__ void agg_kernel(const int* __restrict__ src, const int* __restrict__ et,
                           const float* __restrict__ bias, float* __restrict__ Y)
{
    const int n = blockIdx.x;
    const int h = threadIdx.x;  // 128
    const int beg = g_off[n], end = g_off[n + 1];
    const float m = fdec(g_menc[n]);
    float acc = 0.f, den = 0.f;
    for (int i = beg; i < end; i++) {
        int e = g_sorted[i];
        float w = __expf(g_alpha[e] - m);
        int s = src[e];
        int r = et[e];
        den += w;
        acc += w * g_xw[((size_t)r * NN + s) * HH + h];
    }
    float v = acc / (den + 1e-16f) + bias[h];
    v = fmaxf(v, 0.f);  // both RGAT layers are followed by ReLU
    Y[(size_t)n * HH + h] = v;
}

// ---------------- Wl transpose (final linear uses h @ Wl^T) ----------------
__global__ void transpose_kernel(const float* __restrict__ Wl) {
    int idx = blockIdx.x * blockDim.x + threadIdx.x;  // 16384
    if (idx < HH * HH) {
        int o = idx / HH, hc = idx % HH;
        g_wlt[hc * HH + o] = Wl[o * HH + hc];
    }
}

// ---------------- launch ----------------
extern "C" void kernel_launch(void* const* d_in, const int* in_sizes, int n_in,
                              void* d_out, int out_size)
{
    const float* x  = (const float*)d_in[0];
    const int*   ei = (const int*)d_in[1];
    const int*   et = (const int*)d_in[2];
    // d_in[3] = batch (unused: equal-size sorted graphs -> plain reshape)
    const float* W1 = (const float*)d_in[4];
    const float* q1 = (const float*)d_in[5];
    const float* k1 = (const float*)d_in[6];
    const float* b1 = (const float*)d_in[7];
    const float* W2 = (const float*)d_in[8];
    const float* q2 = (const float*)d_in[9];
    const float* k2 = (const float*)d_in[10];
    const float* b2 = (const float*)d_in[11];
    const float* Wl = (const float*)d_in[12];
    const float* bl = (const float*)d_in[13];
    const int* src = ei;
    const int* tgt = ei + EE;

    float *p_xw, *p_h1, *p_h2, *p_wlt, *p_sq, *p_sk;
    cudaGetSymbolAddress((void**)&p_xw, g_xw);
    cudaGetSymbolAddress((void**)&p_h1, g_h1);
    cudaGetSymbolAddress((void**)&p_h2, g_h2);
    cudaGetSymbolAddress((void**)&p_wlt, g_wlt);
    cudaGetSymbolAddress((void**)&p_sq, g_sq);
    cudaGetSymbolAddress((void**)&p_sk, g_sk);

    const int EB = (EE + 255) / 256;
    const int NB = (NN + 255) / 256;
    const int MB = (NN + 127) / 128;

    // CSR by target (shared by both layers)
    zero_counts_kernel<<<NB, 256>>>();
    hist_kernel<<<EB, 256>>>(tgt);
    scan_kernel<<<1, 1024>>>();
    copy_cursor_kernel<<<NB, 256>>>();
    scatter_kernel<<<EB, 256>>>(tgt);

    transpose_kernel<<<(HH * HH + 255) / 256, 256>>>(Wl);

    // ---- layer 1 ----
    gemm128<<<dim3(MB, RR), 256>>>(x, W1, p_xw, NN, q1, k1, p_sq, p_sk, nullptr);
    minit_kernel<<<NB, 256>>>();
    alpha_kernel<<<EB, 256>>>(src, tgt, et);
    agg_kernel<<<NN, HH>>>(src, et, b1, p_h1);

    // ---- layer 2 ----
    gemm128<<<dim3(MB, RR), 256>>>(p_h1, W2, p_xw, NN, q2, k2, p_sq, p_sk, nullptr);
    minit_kernel<<<NB, 256>>>();
    alpha_kernel<<<EB, 256>>>(src, tgt, et);
    agg_kernel<<<NN, HH>>>(src, et, b2, p_h2);

    // ---- final linear straight into d_out ([B,NPG,H] is contiguous [N,H]) ----
    gemm128<<<dim3(MB, 1), 256>>>(p_h2, p_wlt, (float*)d_out, NN,
                                  nullptr, nullptr, nullptr, nullptr, bl);
}